// round 9
// baseline (speedup 1.0000x reference)
#include <cuda_runtime.h>
#include <math.h>

#define C 64
#define TE 128
#define BT 512
#define SAS 132
#define NOUTC 32
#define NMAX 100000
#define EMAX 1600000
#define SCB 1024

// ---------------- scratch (device globals; no allocation) ----------------
__device__ float g_hA[(size_t)NMAX * C];
__device__ float g_hB[(size_t)NMAX * C];
__device__ float g_xA[(size_t)NMAX * 3];
__device__ float g_hn[(size_t)NMAX * C];
__device__ float g_xs[(size_t)NMAX * 4];
__device__ float g_Ps[(size_t)NMAX * C];
__device__ float g_Pd[(size_t)NMAX * C];
__device__ int   g_cnt[NMAX];
__device__ int   g_cur[NMAX];
__device__ int   g_off[NMAX];
__device__ int   g_bsum[128];
__device__ int   g_esrc[EMAX];
__device__ int   g_edst[EMAX];

// ---------------- helpers ----------------
__device__ __forceinline__ int swz(int row, int col) {
    return col ^ (((row >> 3) & 7) << 2);
}
__device__ __forceinline__ unsigned long long pk2(float x, float y) {
    unsigned long long r;
    asm("mov.b64 %0, {%1, %2};" : "=l"(r) : "f"(x), "f"(y));
    return r;
}
__device__ __forceinline__ float2 up2(unsigned long long v) {
    float lo, hi;
    asm("mov.b64 {%0, %1}, %2;" : "=f"(lo), "=f"(hi) : "l"(v));
    return make_float2(lo, hi);
}
__device__ __forceinline__ void fma2(unsigned long long& d, unsigned long long a, unsigned long long b) {
    asm("fma.rn.f32x2 %0, %1, %2, %0;" : "+l"(d) : "l"(a), "l"(b));
}
__device__ __forceinline__ void redv4(float* p, float a, float b, float c, float d) {
    asm volatile("red.global.add.v4.f32 [%0], {%1, %2, %3, %4};"
                 :: "l"(p), "f"(a), "f"(b), "f"(c), "f"(d) : "memory");
}
__device__ __forceinline__ float siluf(float v) {
    return v * (1.0f / (1.0f + __expf(-v)));
}

// 2 rows x 8 cols accumulator
struct Acc2 { unsigned long long a[2][4]; };

__device__ __forceinline__ void init_bias2(Acc2& acc, const float* bias, int tx8) {
    const ulonglong2* b = reinterpret_cast<const ulonglong2*>(bias + tx8);
    ulonglong2 b01 = b[0], b23 = b[1];
#pragma unroll
    for (int i = 0; i < 2; i++) {
        acc.a[i][0] = b01.x; acc.a[i][1] = b01.y;
        acc.a[i][2] = b23.x; acc.a[i][3] = b23.y;
    }
}
__device__ __forceinline__ void init_zero2(Acc2& acc) {
#pragma unroll
    for (int i = 0; i < 2; i++)
#pragma unroll
        for (int j = 0; j < 4; j++) acc.a[i][j] = 0ull;
}

// A is k-major [KN][tile], swizzled columns, row stride AS; W is [KN][WS] row-major.
template<int KN, int AS, int WS>
__device__ __forceinline__ void gemm_tile2(const float* __restrict__ sA,
                                           const float* __restrict__ sW,
                                           int ty2, int tx8, Acc2& acc) {
#pragma unroll 8
    for (int k = 0; k < KN; k++) {
        float2 av = *reinterpret_cast<const float2*>(sA + k * AS + swz(k, ty2));
        const ulonglong2* bp = reinterpret_cast<const ulonglong2*>(sW + k * WS + tx8);
        ulonglong2 b01 = bp[0];
        ulonglong2 b23 = bp[1];
        unsigned long long a0 = pk2(av.x, av.x);
        fma2(acc.a[0][0], a0, b01.x); fma2(acc.a[0][1], a0, b01.y);
        fma2(acc.a[0][2], a0, b23.x); fma2(acc.a[0][3], a0, b23.y);
        unsigned long long a1 = pk2(av.y, av.y);
        fma2(acc.a[1][0], a1, b01.x); fma2(acc.a[1][1], a1, b01.y);
        fma2(acc.a[1][2], a1, b23.x); fma2(acc.a[1][3], a1, b23.y);
    }
}

__device__ __forceinline__ void unpack2(const Acc2& acc, float r[2][8]) {
#pragma unroll
    for (int i = 0; i < 2; i++)
#pragma unroll
        for (int j = 0; j < 4; j++) {
            float2 v = up2(acc.a[i][j]);
            r[i][2*j] = v.x; r[i][2*j+1] = v.y;
        }
}
__device__ __forceinline__ void silu2(float r[2][8]) {
#pragma unroll
    for (int i = 0; i < 2; i++)
#pragma unroll
        for (int c = 0; c < 8; c++) r[i][c] = siluf(r[i][c]);
}
template<int AS>
__device__ __forceinline__ void store_t2(float* __restrict__ sA, int ty2, int tx8, const float r[2][8]) {
#pragma unroll
    for (int c = 0; c < 8; c++) {
        int row = tx8 + c;
        *reinterpret_cast<float2*>(sA + row * AS + swz(row, ty2)) = make_float2(r[0][c], r[1][c]);
    }
}

// ---------------- sort-by-dst (counting sort, emits packed src/dst) ----------------
__global__ void zero_int_kernel(int* __restrict__ cnt, int* __restrict__ cur, int N) {
    int i = blockIdx.x * blockDim.x + threadIdx.x;
    if (i < N) { cnt[i] = 0; cur[i] = 0; }
}
__global__ void hist_kernel(const int* __restrict__ dst, int* __restrict__ cnt, int E) {
    int e = blockIdx.x * blockDim.x + threadIdx.x;
    if (e < E) atomicAdd(&cnt[dst[e]], 1);
}
__global__ void scan1_kernel(const int* __restrict__ cnt, int* __restrict__ off,
                             int* __restrict__ bsum, int N) {
    __shared__ int sm[256];
    const int t = threadIdx.x;
    const int base = blockIdx.x * SCB + t * 4;
    int c0 = (base+0 < N) ? cnt[base+0] : 0;
    int c1 = (base+1 < N) ? cnt[base+1] : 0;
    int c2 = (base+2 < N) ? cnt[base+2] : 0;
    int c3 = (base+3 < N) ? cnt[base+3] : 0;
    int tot = c0 + c1 + c2 + c3;
    sm[t] = tot;
    __syncthreads();
#pragma unroll
    for (int d = 1; d < 256; d <<= 1) {
        int v = (t >= d) ? sm[t - d] : 0;
        __syncthreads();
        sm[t] += v;
        __syncthreads();
    }
    int ex = sm[t] - tot;
    if (t == 255) bsum[blockIdx.x] = sm[255];
    if (base+0 < N) off[base+0] = ex;
    if (base+1 < N) off[base+1] = ex + c0;
    if (base+2 < N) off[base+2] = ex + c0 + c1;
    if (base+3 < N) off[base+3] = ex + c0 + c1 + c2;
}
__global__ void scan2_kernel(int* __restrict__ bsum, int nb) {
    __shared__ int sm[128];
    int t = threadIdx.x;
    int v = (t < nb) ? bsum[t] : 0;
    sm[t] = v;
    __syncthreads();
#pragma unroll
    for (int d = 1; d < 128; d <<= 1) {
        int u = (t >= d) ? sm[t - d] : 0;
        __syncthreads();
        sm[t] += u;
        __syncthreads();
    }
    if (t < nb) bsum[t] = sm[t] - v;
}
__global__ void scatter_kernel(const int* __restrict__ src, const int* __restrict__ dst,
                               const int* __restrict__ off,
                               const int* __restrict__ bsum, int* __restrict__ cur,
                               int* __restrict__ esrc, int* __restrict__ edst, int E) {
    int e = blockIdx.x * blockDim.x + threadIdx.x;
    if (e < E) {
        int d = dst[e];
        int p = off[d] + bsum[d >> 10] + atomicAdd(&cur[d], 1);
        esrc[p] = src[e];
        edst[p] = d;
    }
}

// ---------------- zero kernel ----------------
__global__ void zero_kernel(float* __restrict__ hn, float* __restrict__ xs, int nh, int nx) {
    int i = blockIdx.x * blockDim.x + threadIdx.x;
    int st = gridDim.x * blockDim.x;
    for (int j = i; j < nh; j += st) hn[j] = 0.0f;
    for (int j = i; j < nx; j += st) xs[j] = 0.0f;
}

// ---------------- per-node precompute: Ps = h@W1s, Pd = h@W1d + b1 ----------------
#define PRE_SMEM_FLOATS (2*C*C + C + C*SAS)
#define PRE_SMEM_BYTES  (PRE_SMEM_FLOATS * 4)

__global__ void __launch_bounds__(BT, 2) pre_kernel(
    const float* __restrict__ h, const float* __restrict__ w1,
    const float* __restrict__ b1,
    float* __restrict__ Ps, float* __restrict__ Pd, int N)
{
    extern __shared__ float sm[];
    float* sWs = sm;
    float* sWd = sWs + C*C;
    float* sB1 = sWd + C*C;
    float* sA  = sB1 + C;

    const int tid = threadIdx.x;
    for (int i = tid; i < C*C; i += BT) { sWs[i] = w1[i]; sWd[i] = w1[C*C + i]; }
    if (tid < C) sB1[tid] = b1[tid];

    const int base = blockIdx.x * TE;
    {
        const int el = tid >> 2, q = tid & 3;
        const int n = base + el;
        const bool v = (n < N);
        const float4 z4 = make_float4(0.f, 0.f, 0.f, 0.f);
#pragma unroll
        for (int i = 0; i < 4; i++) {
            int k = q*16 + i*4;
            float4 vh = v ? *reinterpret_cast<const float4*>(h + (size_t)n*C + k) : z4;
            sA[(k+0)*SAS + swz(k+0, el)] = vh.x;
            sA[(k+1)*SAS + swz(k+1, el)] = vh.y;
            sA[(k+2)*SAS + swz(k+2, el)] = vh.z;
            sA[(k+3)*SAS + swz(k+3, el)] = vh.w;
        }
    }
    __syncthreads();

    const int tx8 = (tid & 7) * 8;
    const int ty2 = (tid >> 3) * 2;

    Acc2 acc;
    init_zero2(acc);
    gemm_tile2<C, SAS, C>(sA, sWs, ty2, tx8, acc);
    float r[2][8];
    unpack2(acc, r);
#pragma unroll
    for (int i = 0; i < 2; i++) {
        int n = base + ty2 + i;
        if (n < N) {
            float* p = Ps + (size_t)n*C + tx8;
            *reinterpret_cast<float4*>(p)     = make_float4(r[i][0], r[i][1], r[i][2], r[i][3]);
            *reinterpret_cast<float4*>(p + 4) = make_float4(r[i][4], r[i][5], r[i][6], r[i][7]);
        }
    }
    init_bias2(acc, sB1, tx8);
    gemm_tile2<C, SAS, C>(sA, sWd, ty2, tx8, acc);
    unpack2(acc, r);
#pragma unroll
    for (int i = 0; i < 2; i++) {
        int n = base + ty2 + i;
        if (n < N) {
            float* p = Pd + (size_t)n*C + tx8;
            *reinterpret_cast<float4*>(p)     = make_float4(r[i][0], r[i][1], r[i][2], r[i][3]);
            *reinterpret_cast<float4*>(p + 4) = make_float4(r[i][4], r[i][5], r[i][6], r[i][7]);
        }
    }
}

// ---------------- edge kernel (edges pre-sorted by dst; packed esrc/edst) ----------------
#define EDGE_SMEM_FLOATS (C*C + C + C*C + C + C + C + C*SAS + 3*TE + TE)
#define EDGE_SMEM_BYTES  (EDGE_SMEM_FLOATS * 4)

__global__ void __launch_bounds__(BT, 2) edge_kernel(
    const float* __restrict__ Ps, const float* __restrict__ Pd,
    const float* __restrict__ w1r,
    const float* __restrict__ x,
    const int* __restrict__ esrc, const int* __restrict__ edst,
    const float* __restrict__ ew2, const float* __restrict__ eb2,
    const float* __restrict__ cw1, const float* __restrict__ cb1,
    const float* __restrict__ cw2,
    float* __restrict__ hn, float* __restrict__ xs, int E, int do_coord)
{
    extern __shared__ float sm[];
    float* sW2  = sm;
    float* sB2  = sW2 + C*C;
    float* sC1  = sB2 + C;
    float* sCB1 = sC1 + C*C;
    float* sC2  = sCB1 + C;
    float* sW1r = sC2 + C;
    float* sA   = sW1r + C;      // 64 x 132 (k-major, swizzled)
    float* sXd  = sA + C*SAS;    // [3][TE]
    int*   sDst = (int*)(sXd + 3*TE);

    const int tid = threadIdx.x;
    for (int i = tid; i < C*C; i += BT) { sW2[i] = ew2[i]; sC1[i] = cw1[i]; }
    if (tid < C) { sB2[tid] = eb2[tid]; sCB1[tid] = cb1[tid]; sC2[tid] = cw2[tid]; sW1r[tid] = w1r[tid]; }

    const int tx8 = (tid & 7) * 8;
    const int ty2 = (tid >> 3) * 2;
    const int ntiles = (E + TE - 1) / TE;

    for (int tile = blockIdx.x; tile < ntiles; tile += gridDim.x) {
        __syncthreads();
        const int e0 = tile * TE;

        // gather + fused GEMM1 replacement: f1 = silu(Ps[src] + Pd[dst] + radial*w1r)
        {
            const int el = tid >> 2, q = tid & 3;
            const bool v = (e0 + el < E);
            const int s = v ? esrc[e0 + el] : 0;
            const int d = v ? edst[e0 + el] : 0;
            if (q == 0) sDst[el] = v ? d : -1;
            float dx = x[3*s+0] - x[3*d+0];
            float dy = x[3*s+1] - x[3*d+1];
            float dz = x[3*s+2] - x[3*d+2];
            float rad = dx*dx + dy*dy + dz*dz;
            if (do_coord && q == 0) {
                float inv = 1.0f / (sqrtf(rad) + 1e-30f);
                sXd[el] = dx*inv; sXd[TE+el] = dy*inv; sXd[2*TE+el] = dz*inv;
            }
            const float* ps = Ps + (size_t)s*C + q*16;
            const float* pd = Pd + (size_t)d*C + q*16;
            const float4 z4 = make_float4(0.f, 0.f, 0.f, 0.f);
#pragma unroll
            for (int i = 0; i < 4; i++) {
                int k = q*16 + i*4;
                float4 a = v ? *reinterpret_cast<const float4*>(ps + i*4) : z4;
                float4 b = v ? *reinterpret_cast<const float4*>(pd + i*4) : z4;
                float4 w = *reinterpret_cast<const float4*>(sW1r + k);
                sA[(k+0)*SAS + swz(k+0, el)] = siluf(a.x + b.x + rad*w.x);
                sA[(k+1)*SAS + swz(k+1, el)] = siluf(a.y + b.y + rad*w.y);
                sA[(k+2)*SAS + swz(k+2, el)] = siluf(a.z + b.z + rad*w.z);
                sA[(k+3)*SAS + swz(k+3, el)] = siluf(a.w + b.w + rad*w.w);
            }
        }
        __syncthreads();

        // GEMM2: msg_h = silu(f1 @ W2 + b2)
        Acc2 acc;
        init_bias2(acc, sB2, tx8);
        gemm_tile2<C, SAS, C>(sA, sW2, ty2, tx8, acc);
        float mh[2][8];
        unpack2(acc, mh);
        silu2(mh);

        // pair-merged scatter (dst sorted)
        {
            int d0 = sDst[ty2], d1 = sDst[ty2+1];
            if (d0 == d1) {
                if (d0 >= 0) {
                    float* p = hn + (size_t)d0*C + tx8;
                    redv4(p,     mh[0][0]+mh[1][0], mh[0][1]+mh[1][1], mh[0][2]+mh[1][2], mh[0][3]+mh[1][3]);
                    redv4(p + 4, mh[0][4]+mh[1][4], mh[0][5]+mh[1][5], mh[0][6]+mh[1][6], mh[0][7]+mh[1][7]);
                }
            } else {
                if (d0 >= 0) {
                    float* p = hn + (size_t)d0*C + tx8;
                    redv4(p,     mh[0][0], mh[0][1], mh[0][2], mh[0][3]);
                    redv4(p + 4, mh[0][4], mh[0][5], mh[0][6], mh[0][7]);
                }
                if (d1 >= 0) {
                    float* p = hn + (size_t)d1*C + tx8;
                    redv4(p,     mh[1][0], mh[1][1], mh[1][2], mh[1][3]);
                    redv4(p + 4, mh[1][4], mh[1][5], mh[1][6], mh[1][7]);
                }
            }
        }

        if (!do_coord) continue;

        __syncthreads();
        store_t2<SAS>(sA, ty2, tx8, mh);
        __syncthreads();

        // GEMM3: q = silu(msg_h @ CW1 + cb1); coord_s = q . cw2
        init_bias2(acc, sCB1, tx8);
        gemm_tile2<C, SAS, C>(sA, sC1, ty2, tx8, acc);
        float qv[2][8];
        unpack2(acc, qv);
        silu2(qv);
        float c2[8];
#pragma unroll
        for (int j = 0; j < 8; j++) c2[j] = sC2[tx8 + j];
        float csum[2];
#pragma unroll
        for (int i = 0; i < 2; i++) {
            float s = 0.f;
#pragma unroll
            for (int j = 0; j < 8; j++) s += qv[i][j] * c2[j];
            csum[i] = s;
        }
#pragma unroll
        for (int m = 1; m < 8; m <<= 1) {
#pragma unroll
            for (int i = 0; i < 2; i++)
                csum[i] += __shfl_xor_sync(0xffffffffu, csum[i], m);
        }
        if ((tid & 7) == 0) {
            int d0 = sDst[ty2], d1 = sDst[ty2+1];
            float vx0 = csum[0]*sXd[ty2],   vy0 = csum[0]*sXd[TE+ty2],   vz0 = csum[0]*sXd[2*TE+ty2];
            float vx1 = csum[1]*sXd[ty2+1], vy1 = csum[1]*sXd[TE+ty2+1], vz1 = csum[1]*sXd[2*TE+ty2+1];
            if (d0 == d1) {
                if (d0 >= 0) redv4(xs + (size_t)d0*4, vx0+vx1, vy0+vy1, vz0+vz1, 0.0f);
            } else {
                if (d0 >= 0) redv4(xs + (size_t)d0*4, vx0, vy0, vz0, 0.0f);
                if (d1 >= 0) redv4(xs + (size_t)d1*4, vx1, vy1, vz1, 0.0f);
            }
        }
    }
}

// ---------------- node kernel (sH aliases sA rows 0..63 after GEMM1) ----------------
#define NODE_SMEM_FLOATS (2*C*C + C + C*C + C + C + C + 2*C*SAS)
#define NODE_SMEM_BYTES  (NODE_SMEM_FLOATS * 4)

__global__ void __launch_bounds__(BT, 1) node_kernel(
    const float* __restrict__ h, const float* __restrict__ x,
    const float* __restrict__ hn, const float* __restrict__ xs,
    const int* __restrict__ cnt,
    const float* __restrict__ nw1, const float* __restrict__ nb1,
    const float* __restrict__ nw2, const float* __restrict__ nb2,
    const float* __restrict__ lng, const float* __restrict__ lnb,
    float* __restrict__ h_out, float* __restrict__ x_out, int N, int do_x)
{
    extern __shared__ float sm[];
    float* sW1 = sm;
    float* sB1 = sW1 + 2*C*C;
    float* sW2 = sB1 + C;
    float* sB2 = sW2 + C*C;
    float* sLG = sB2 + C;
    float* sLB = sLG + C;
    float* sA  = sLB + C;      // 128 x 132 (k-major, swizzled); rows 0..63 reused as sH
    float* sH  = sA;

    const int tid = threadIdx.x;
    for (int i = tid; i < 2*C*C; i += BT) sW1[i] = nw1[i];
    for (int i = tid; i < C*C; i += BT) sW2[i] = nw2[i];
    if (tid < C) { sB1[tid] = nb1[tid]; sB2[tid] = nb2[tid]; sLG[tid] = lng[tid]; sLB[tid] = lnb[tid]; }

    const int tx8 = (tid & 7) * 8;
    const int ty2 = (tid >> 3) * 2;
    const int base = blockIdx.x * TE;

    if (do_x && tid < TE) {
        int n = base + tid;
        if (n < N) {
            float4 s = *reinterpret_cast<const float4*>(xs + (size_t)n*4);
            float deg = fmaxf((float)cnt[n], 1.0f);
            x_out[3*n+0] = x[3*n+0] + s.x / deg;
            x_out[3*n+1] = x[3*n+1] + s.y / deg;
            x_out[3*n+2] = x[3*n+2] + s.z / deg;
        }
    }

    {
        const int el = tid >> 2, q = tid & 3;
        const int n = base + el;
        const bool v = (n < N);
        const float4 z4 = make_float4(0.f, 0.f, 0.f, 0.f);
#pragma unroll
        for (int i = 0; i < 4; i++) {
            int k = q*16 + i*4;
            float4 vh = v ? *reinterpret_cast<const float4*>(h  + (size_t)n*C + k) : z4;
            float4 vn = v ? *reinterpret_cast<const float4*>(hn + (size_t)n*C + k) : z4;
            sA[(k+0)*SAS + swz(k+0, el)] = vh.x;
            sA[(k+1)*SAS + swz(k+1, el)] = vh.y;
            sA[(k+2)*SAS + swz(k+2, el)] = vh.z;
            sA[(k+3)*SAS + swz(k+3, el)] = vh.w;
            sA[(C+k+0)*SAS + swz(C+k+0, el)] = vn.x;
            sA[(C+k+1)*SAS + swz(C+k+1, el)] = vn.y;
            sA[(C+k+2)*SAS + swz(C+k+2, el)] = vn.z;
            sA[(C+k+3)*SAS + swz(C+k+3, el)] = vn.w;
        }
    }
    __syncthreads();

    Acc2 acc;
    init_bias2(acc, sB1, tx8);
    gemm_tile2<2*C, SAS, C>(sA, sW1, ty2, tx8, acc);
    __syncthreads();
    float r1[2][8];
    unpack2(acc, r1);
    silu2(r1);
    store_t2<SAS>(sH, ty2, tx8, r1);   // overwrites sA rows 0..63 (safe after barrier)
    __syncthreads();

    init_bias2(acc, sB2, tx8);
    gemm_tile2<C, SAS, C>(sH, sW2, ty2, tx8, acc);
    float r2[2][8];
    unpack2(acc, r2);

#pragma unroll
    for (int i = 0; i < 2; i++) {
        float s1 = 0.f, s2 = 0.f;
#pragma unroll
        for (int c = 0; c < 8; c++) {
            float v = r2[i][c];
            v = 0.5f * v * (1.0f + erff(v * 0.70710678118654752f));
            r2[i][c] = v;
            s1 += v; s2 += v*v;
        }
#pragma unroll
        for (int m = 1; m < 8; m <<= 1) {
            s1 += __shfl_xor_sync(0xffffffffu, s1, m);
            s2 += __shfl_xor_sync(0xffffffffu, s2, m);
        }
        float mu = s1 * (1.0f / C);
        float var = s2 * (1.0f / C) - mu * mu;
        float inv = rsqrtf(var + 1e-5f);
        int n = base + ty2 + i;
        if (n < N) {
            float o[8];
#pragma unroll
            for (int c = 0; c < 8; c++)
                o[c] = (r2[i][c] - mu) * inv * sLG[tx8 + c] + sLB[tx8 + c];
            float* p = h_out + (size_t)n*C + tx8;
            *reinterpret_cast<float4*>(p)     = make_float4(o[0], o[1], o[2], o[3]);
            *reinterpret_cast<float4*>(p + 4) = make_float4(o[4], o[5], o[6], o[7]);
        }
    }
}

// ---------------- output head ----------------
#define OTILE 256
#define OAS 260
#define OUT_SMEM_FLOATS (C*OAS + C*NOUTC + NOUTC)
#define OUT_SMEM_BYTES  (OUT_SMEM_FLOATS * 4)

__global__ void __launch_bounds__(BT, 2) out_kernel(
    const float* __restrict__ h, const float* __restrict__ ow,
    const float* __restrict__ ob, float* __restrict__ out, int N)
{
    extern __shared__ float sm[];
    float* sA = sm;
    float* sW = sA + C*OAS;
    float* sB = sW + C*NOUTC;

    const int tid = threadIdx.x;
    for (int i = tid; i < C*NOUTC; i += BT) sW[i] = ow[i];
    if (tid < NOUTC) sB[tid] = ob[tid];

    const int base = blockIdx.x * OTILE;
    {
        const float4* hg = reinterpret_cast<const float4*>(h + (size_t)base * C);
        const float4 z4 = make_float4(0.f, 0.f, 0.f, 0.f);
        for (int idx = tid; idx < OTILE * (C/4); idx += BT) {
            int p = idx * 4;
            int ln = p >> 6;
            int k = p & 63;
            float4 v = (base + ln < N) ? hg[idx] : z4;
            sA[(k+0)*OAS + swz(k+0, ln)] = v.x;
            sA[(k+1)*OAS + swz(k+1, ln)] = v.y;
            sA[(k+2)*OAS + swz(k+2, ln)] = v.z;
            sA[(k+3)*OAS + swz(k+3, ln)] = v.w;
        }
    }
    __syncthreads();

    const int tx8 = (tid & 3) * 8;
    const int ty2 = (tid >> 2) * 2;
    Acc2 acc;
    init_bias2(acc, sB, tx8);
    gemm_tile2<C, OAS, NOUTC>(sA, sW, ty2, tx8, acc);
    float r[2][8];
    unpack2(acc, r);
#pragma unroll
    for (int i = 0; i < 2; i++) {
        int n = base + ty2 + i;
        if (n < N) {
            float* p = out + (size_t)n * NOUTC + tx8;
            *reinterpret_cast<float4*>(p)     = make_float4(r[i][0], r[i][1], r[i][2], r[i][3]);
            *reinterpret_cast<float4*>(p + 4) = make_float4(r[i][4], r[i][5], r[i][6], r[i][7]);
        }
    }
}

// ---------------- launch ----------------
extern "C" void kernel_launch(void* const* d_in, const int* in_sizes, int n_in,
                              void* d_out, int out_size) {
    const float* node_feat = (const float*)d_in[0];
    const float* xyz = (const float*)d_in[1];
    const int* src = (const int*)d_in[2];
    const int* dst = (const int*)d_in[3];
    const float* ew1 = (const float*)d_in[4];
    const float* eb1 = (const float*)d_in[5];
    const float* ew2 = (const float*)d_in[6];
    const float* eb2 = (const float*)d_in[7];
    const float* cw1 = (const float*)d_in[8];
    const float* cb1 = (const float*)d_in[9];
    const float* cw2 = (const float*)d_in[10];
    const float* nw1 = (const float*)d_in[11];
    const float* nb1 = (const float*)d_in[12];
    const float* nw2 = (const float*)d_in[13];
    const float* nb2 = (const float*)d_in[14];
    const float* lng = (const float*)d_in[15];
    const float* lnb = (const float*)d_in[16];
    const float* ow  = (const float*)d_in[17];
    const float* ob  = (const float*)d_in[18];

    const int N = in_sizes[0] / C;
    const int E = in_sizes[2];

    float *hA, *hB, *xA, *hn, *xs, *Ps, *Pd;
    int *cnt, *cur, *off, *bsum, *esrc, *edst;
    cudaGetSymbolAddress((void**)&hA, g_hA);
    cudaGetSymbolAddress((void**)&hB, g_hB);
    cudaGetSymbolAddress((void**)&xA, g_xA);
    cudaGetSymbolAddress((void**)&hn, g_hn);
    cudaGetSymbolAddress((void**)&xs, g_xs);
    cudaGetSymbolAddress((void**)&Ps, g_Ps);
    cudaGetSymbolAddress((void**)&Pd, g_Pd);
    cudaGetSymbolAddress((void**)&cnt, g_cnt);
    cudaGetSymbolAddress((void**)&cur, g_cur);
    cudaGetSymbolAddress((void**)&off, g_off);
    cudaGetSymbolAddress((void**)&bsum, g_bsum);
    cudaGetSymbolAddress((void**)&esrc, g_esrc);
    cudaGetSymbolAddress((void**)&edst, g_edst);

    cudaFuncSetAttribute(pre_kernel,  cudaFuncAttributeMaxDynamicSharedMemorySize, PRE_SMEM_BYTES);
    cudaFuncSetAttribute(edge_kernel, cudaFuncAttributeMaxDynamicSharedMemorySize, EDGE_SMEM_BYTES);
    cudaFuncSetAttribute(node_kernel, cudaFuncAttributeMaxDynamicSharedMemorySize, NODE_SMEM_BYTES);
    cudaFuncSetAttribute(out_kernel,  cudaFuncAttributeMaxDynamicSharedMemorySize, OUT_SMEM_BYTES);

    const int ntiles_n = (N + TE - 1) / TE;
    const int ntiles_o = (N + OTILE - 1) / OTILE;
    const int nb = (N + SCB - 1) / SCB;

    // counting sort of edges by dst -> packed esrc/edst (reused by both layers)
    zero_int_kernel<<<(N + 255) / 256, 256>>>(cnt, cur, N);
    hist_kernel<<<(E + 255) / 256, 256>>>(dst, cnt, E);
    scan1_kernel<<<nb, 256>>>(cnt, off, bsum, N);
    scan2_kernel<<<1, 128>>>(bsum, nb);
    scatter_kernel<<<(E + 255) / 256, 256>>>(src, dst, off, bsum, cur, esrc, edst, E);

    // layer 0
    pre_kernel<<<ntiles_n, BT, PRE_SMEM_BYTES>>>(node_feat, ew1, eb1, Ps, Pd, N);
    zero_kernel<<<512, 256>>>(hn, xs, N*C, N*4);
    edge_kernel<<<296, BT, EDGE_SMEM_BYTES>>>(Ps, Pd, ew1 + 128*C, xyz, esrc, edst,
        ew2, eb2, cw1, cb1, cw2, hn, xs, E, 1);
    node_kernel<<<ntiles_n, BT, NODE_SMEM_BYTES>>>(node_feat, xyz, hn, xs, cnt,
        nw1, nb1, nw2, nb2, lng, lnb, hA, xA, N, 1);

    // layer 1 (coord path + x update dead w.r.t. output -> skipped)
    pre_kernel<<<ntiles_n, BT, PRE_SMEM_BYTES>>>(hA, ew1 + 129*C, eb1 + C, Ps, Pd, N);
    zero_kernel<<<512, 256>>>(hn, xs, N*C, 0);
    edge_kernel<<<296, BT, EDGE_SMEM_BYTES>>>(Ps, Pd, ew1 + 129*C + 128*C, xA, esrc, edst,
        ew2 + C*C, eb2 + C, cw1 + C*C, cb1 + C, cw2 + C, hn, xs, E, 0);
    node_kernel<<<ntiles_n, BT, NODE_SMEM_BYTES>>>(hA, xA, hn, xs, cnt,
        nw1 + 2*C*C, nb1 + C, nw2 + C*C, nb2 + C, lng, lnb, hB, xA, N, 0);

    out_kernel<<<ntiles_o, BT, OUT_SMEM_BYTES>>>(hB, ow, ob, (float*)d_out, N);
}

// round 12
// speedup vs baseline: 1.4479x; 1.4479x over previous
#include <cuda_runtime.h>
#include <math.h>

#define C 64
#define TE 128
#define BT 256
#define SAS 132
#define NOUTC 32
#define NMAX 100000
#define EMAX 1600000
#define SCB 1024

// ---------------- scratch (device globals; no allocation) ----------------
__device__ float g_hA[(size_t)NMAX * C];
__device__ float g_hB[(size_t)NMAX * C];
__device__ float g_xA[(size_t)NMAX * 3];
__device__ float g_hn[(size_t)NMAX * C];
__device__ float g_xs[(size_t)NMAX * 4];
__device__ float g_Ps[(size_t)NMAX * C];
__device__ float g_Pd[(size_t)NMAX * C];
__device__ int   g_cnt[NMAX];
__device__ int   g_cur[NMAX];
__device__ int   g_off[NMAX];
__device__ int   g_bsum[128];
__device__ int   g_esrc[EMAX];
__device__ int   g_edst[EMAX];

// ---------------- helpers ----------------
__device__ __forceinline__ int swz(int row, int col) {
    return col ^ (((row >> 3) & 7) << 2);
}
__device__ __forceinline__ unsigned long long pk2(float x, float y) {
    unsigned long long r;
    asm("mov.b64 %0, {%1, %2};" : "=l"(r) : "f"(x), "f"(y));
    return r;
}
__device__ __forceinline__ float2 up2(unsigned long long v) {
    float lo, hi;
    asm("mov.b64 {%0, %1}, %2;" : "=f"(lo), "=f"(hi) : "l"(v));
    return make_float2(lo, hi);
}
__device__ __forceinline__ void fma2(unsigned long long& d, unsigned long long a, unsigned long long b) {
    asm("fma.rn.f32x2 %0, %1, %2, %0;" : "+l"(d) : "l"(a), "l"(b));
}
__device__ __forceinline__ void redv4(float* p, float a, float b, float c, float d) {
    asm volatile("red.global.add.v4.f32 [%0], {%1, %2, %3, %4};"
                 :: "l"(p), "f"(a), "f"(b), "f"(c), "f"(d) : "memory");
}
__device__ __forceinline__ float siluf(float v) {
    return v * (1.0f / (1.0f + __expf(-v)));
}

struct Acc { unsigned long long a[4][4]; };

__device__ __forceinline__ void init_bias(Acc& acc, const float* bias, int tx8) {
    const ulonglong2* b = reinterpret_cast<const ulonglong2*>(bias + tx8);
    ulonglong2 b01 = b[0], b23 = b[1];
#pragma unroll
    for (int i = 0; i < 4; i++) {
        acc.a[i][0] = b01.x; acc.a[i][1] = b01.y;
        acc.a[i][2] = b23.x; acc.a[i][3] = b23.y;
    }
}
__device__ __forceinline__ void init_zero(Acc& acc) {
#pragma unroll
    for (int i = 0; i < 4; i++)
#pragma unroll
        for (int j = 0; j < 4; j++) acc.a[i][j] = 0ull;
}

// A is k-major [KN][tile], swizzled columns, row stride AS; W is [KN][WS] row-major.
template<int KN, int AS, int WS>
__device__ __forceinline__ void gemm_tile(const float* __restrict__ sA,
                                          const float* __restrict__ sW,
                                          int ty4, int tx8, Acc& acc) {
#pragma unroll 8
    for (int k = 0; k < KN; k++) {
        float4 av = *reinterpret_cast<const float4*>(sA + k * AS + swz(k, ty4));
        const ulonglong2* bp = reinterpret_cast<const ulonglong2*>(sW + k * WS + tx8);
        ulonglong2 b01 = bp[0];
        ulonglong2 b23 = bp[1];
        unsigned long long a0 = pk2(av.x, av.x);
        fma2(acc.a[0][0], a0, b01.x); fma2(acc.a[0][1], a0, b01.y);
        fma2(acc.a[0][2], a0, b23.x); fma2(acc.a[0][3], a0, b23.y);
        unsigned long long a1 = pk2(av.y, av.y);
        fma2(acc.a[1][0], a1, b01.x); fma2(acc.a[1][1], a1, b01.y);
        fma2(acc.a[1][2], a1, b23.x); fma2(acc.a[1][3], a1, b23.y);
        unsigned long long a2 = pk2(av.z, av.z);
        fma2(acc.a[2][0], a2, b01.x); fma2(acc.a[2][1], a2, b01.y);
        fma2(acc.a[2][2], a2, b23.x); fma2(acc.a[2][3], a2, b23.y);
        unsigned long long a3 = pk2(av.w, av.w);
        fma2(acc.a[3][0], a3, b01.x); fma2(acc.a[3][1], a3, b01.y);
        fma2(acc.a[3][2], a3, b23.x); fma2(acc.a[3][3], a3, b23.y);
    }
}

__device__ __forceinline__ void unpack_acc(const Acc& acc, float r[4][8]) {
#pragma unroll
    for (int i = 0; i < 4; i++)
#pragma unroll
        for (int j = 0; j < 4; j++) {
            float2 v = up2(acc.a[i][j]);
            r[i][2*j] = v.x; r[i][2*j+1] = v.y;
        }
}
__device__ __forceinline__ void silu_r(float r[4][8]) {
#pragma unroll
    for (int i = 0; i < 4; i++)
#pragma unroll
        for (int c = 0; c < 8; c++) r[i][c] = siluf(r[i][c]);
}
template<int AS>
__device__ __forceinline__ void store_t(float* __restrict__ sA, int ty4, int tx8, const float r[4][8]) {
#pragma unroll
    for (int c = 0; c < 8; c++) {
        int row = tx8 + c;
        float4 v = make_float4(r[0][c], r[1][c], r[2][c], r[3][c]);
        *reinterpret_cast<float4*>(sA + row * AS + swz(row, ty4)) = v;
    }
}

// ---------------- sort-by-dst (counting sort, emits packed src/dst) ----------------
__global__ void zero_int_kernel(int* __restrict__ cnt, int* __restrict__ cur, int N) {
    int i = blockIdx.x * blockDim.x + threadIdx.x;
    if (i < N) { cnt[i] = 0; cur[i] = 0; }
}
__global__ void hist_kernel(const int* __restrict__ dst, int* __restrict__ cnt, int E) {
    int e = blockIdx.x * blockDim.x + threadIdx.x;
    if (e < E) atomicAdd(&cnt[dst[e]], 1);
}
__global__ void scan1_kernel(const int* __restrict__ cnt, int* __restrict__ off,
                             int* __restrict__ bsum, int N) {
    __shared__ int sm[256];
    const int t = threadIdx.x;
    const int base = blockIdx.x * SCB + t * 4;
    int c0 = (base+0 < N) ? cnt[base+0] : 0;
    int c1 = (base+1 < N) ? cnt[base+1] : 0;
    int c2 = (base+2 < N) ? cnt[base+2] : 0;
    int c3 = (base+3 < N) ? cnt[base+3] : 0;
    int tot = c0 + c1 + c2 + c3;
    sm[t] = tot;
    __syncthreads();
#pragma unroll
    for (int d = 1; d < 256; d <<= 1) {
        int v = (t >= d) ? sm[t - d] : 0;
        __syncthreads();
        sm[t] += v;
        __syncthreads();
    }
    int ex = sm[t] - tot;
    if (t == 255) bsum[blockIdx.x] = sm[255];
    if (base+0 < N) off[base+0] = ex;
    if (base+1 < N) off[base+1] = ex + c0;
    if (base+2 < N) off[base+2] = ex + c0 + c1;
    if (base+3 < N) off[base+3] = ex + c0 + c1 + c2;
}
__global__ void scan2_kernel(int* __restrict__ bsum, int nb) {
    __shared__ int sm[128];
    int t = threadIdx.x;
    int v = (t < nb) ? bsum[t] : 0;
    sm[t] = v;
    __syncthreads();
#pragma unroll
    for (int d = 1; d < 128; d <<= 1) {
        int u = (t >= d) ? sm[t - d] : 0;
        __syncthreads();
        sm[t] += u;
        __syncthreads();
    }
    if (t < nb) bsum[t] = sm[t] - v;
}
__global__ void scatter_kernel(const int* __restrict__ src, const int* __restrict__ dst,
                               const int* __restrict__ off,
                               const int* __restrict__ bsum, int* __restrict__ cur,
                               int* __restrict__ esrc, int* __restrict__ edst, int E) {
    int e = blockIdx.x * blockDim.x + threadIdx.x;
    if (e < E) {
        int d = dst[e];
        int p = off[d] + bsum[d >> 10] + atomicAdd(&cur[d], 1);
        esrc[p] = src[e];
        edst[p] = d;
    }
}

// ---------------- zero kernel ----------------
__global__ void zero_kernel(float* __restrict__ hn, float* __restrict__ xs, int nh, int nx) {
    int i = blockIdx.x * blockDim.x + threadIdx.x;
    int st = gridDim.x * blockDim.x;
    for (int j = i; j < nh; j += st) hn[j] = 0.0f;
    for (int j = i; j < nx; j += st) xs[j] = 0.0f;
}

// ---------------- per-node precompute: Ps = h@W1s, Pd = h@W1d + b1 ----------------
#define PRE_SMEM_FLOATS (2*C*C + C + C*SAS)
#define PRE_SMEM_BYTES  (PRE_SMEM_FLOATS * 4)

__global__ void __launch_bounds__(BT, 2) pre_kernel(
    const float* __restrict__ h, const float* __restrict__ w1,
    const float* __restrict__ b1,
    float* __restrict__ Ps, float* __restrict__ Pd, int N)
{
    extern __shared__ float sm[];
    float* sWs = sm;
    float* sWd = sWs + C*C;
    float* sB1 = sWd + C*C;
    float* sA  = sB1 + C;

    const int tid = threadIdx.x;
    for (int i = tid; i < C*C; i += BT) { sWs[i] = w1[i]; sWd[i] = w1[C*C + i]; }
    if (tid < C) sB1[tid] = b1[tid];

    const int base = blockIdx.x * TE;
    // stage h tile (flat coalesced)
    {
        const float4* hg = reinterpret_cast<const float4*>(h + (size_t)base * C);
        const float4 z4 = make_float4(0.f, 0.f, 0.f, 0.f);
        for (int idx = tid; idx < TE * (C/4); idx += BT) {
            int p = idx * 4;
            int ln = p >> 6;
            int k = p & 63;
            float4 v = (base + ln < N) ? hg[idx] : z4;
            sA[(k+0)*SAS + swz(k+0, ln)] = v.x;
            sA[(k+1)*SAS + swz(k+1, ln)] = v.y;
            sA[(k+2)*SAS + swz(k+2, ln)] = v.z;
            sA[(k+3)*SAS + swz(k+3, ln)] = v.w;
        }
    }
    __syncthreads();

    const int tx8 = (tid & 7) * 8;
    const int ty4 = (tid >> 3) * 4;

    Acc acc;
    init_zero(acc);
    gemm_tile<C, SAS, C>(sA, sWs, ty4, tx8, acc);
    float r[4][8];
    unpack_acc(acc, r);
#pragma unroll
    for (int i = 0; i < 4; i++) {
        int n = base + ty4 + i;
        if (n < N) {
            float* p = Ps + (size_t)n*C + tx8;
            *reinterpret_cast<float4*>(p)     = make_float4(r[i][0], r[i][1], r[i][2], r[i][3]);
            *reinterpret_cast<float4*>(p + 4) = make_float4(r[i][4], r[i][5], r[i][6], r[i][7]);
        }
    }
    init_bias(acc, sB1, tx8);
    gemm_tile<C, SAS, C>(sA, sWd, ty4, tx8, acc);
    unpack_acc(acc, r);
#pragma unroll
    for (int i = 0; i < 4; i++) {
        int n = base + ty4 + i;
        if (n < N) {
            float* p = Pd + (size_t)n*C + tx8;
            *reinterpret_cast<float4*>(p)     = make_float4(r[i][0], r[i][1], r[i][2], r[i][3]);
            *reinterpret_cast<float4*>(p + 4) = make_float4(r[i][4], r[i][5], r[i][6], r[i][7]);
        }
    }
}

// ---------------- edge kernel (edges pre-sorted by dst; packed esrc/edst) ----------------
#define EDGE_SMEM_FLOATS (C*C + C + C*C + C + C + C + C*SAS + 3*TE + TE + TE + TE)
#define EDGE_SMEM_BYTES  (EDGE_SMEM_FLOATS * 4)

__global__ void __launch_bounds__(BT, 2) edge_kernel(
    const float* __restrict__ Ps, const float* __restrict__ Pd,
    const float* __restrict__ w1r,
    const float* __restrict__ x,
    const int* __restrict__ esrc, const int* __restrict__ edst,
    const float* __restrict__ ew2, const float* __restrict__ eb2,
    const float* __restrict__ cw1, const float* __restrict__ cb1,
    const float* __restrict__ cw2,
    float* __restrict__ hn, float* __restrict__ xs, int E, int do_coord)
{
    extern __shared__ float sm[];
    float* sW2  = sm;
    float* sB2  = sW2 + C*C;
    float* sC1  = sB2 + C;
    float* sCB1 = sC1 + C*C;
    float* sC2  = sCB1 + C;
    float* sW1r = sC2 + C;
    float* sA   = sW1r + C;      // 64 x 132 (k-major, swizzled)
    float* sXd  = sA + C*SAS;    // [3][TE]
    float* sRad = sXd + 3*TE;    // [TE]
    int*   sSrc = (int*)(sRad + TE);
    int*   sDst = sSrc + TE;

    const int tid = threadIdx.x;
    for (int i = tid; i < C*C; i += BT) { sW2[i] = ew2[i]; sC1[i] = cw1[i]; }
    if (tid < C) { sB2[tid] = eb2[tid]; sCB1[tid] = cb1[tid]; sC2[tid] = cw2[tid]; sW1r[tid] = w1r[tid]; }

    const int tx8 = (tid & 7) * 8;
    const int ty4 = (tid >> 3) * 4;
    const int ntiles = (E + TE - 1) / TE;

    for (int tile = blockIdx.x; tile < ntiles; tile += gridDim.x) {
        __syncthreads();
        const int e0 = tile * TE;

        // phase A: per-edge geometry + index staging
        if (tid < TE) {
            int e = e0 + tid;
            if (e < E) {
                int s = esrc[e], d = edst[e];
                sSrc[tid] = s; sDst[tid] = d;
                float dx = x[3*s+0] - x[3*d+0];
                float dy = x[3*s+1] - x[3*d+1];
                float dz = x[3*s+2] - x[3*d+2];
                float rad = dx*dx + dy*dy + dz*dz;
                sRad[tid] = rad;
                if (do_coord) {
                    float inv = 1.0f / (sqrtf(rad) + 1e-30f);
                    sXd[tid] = dx*inv; sXd[TE+tid] = dy*inv; sXd[2*TE+tid] = dz*inv;
                }
            } else {
                sSrc[tid] = 0; sDst[tid] = -1; sRad[tid] = 0.0f;
                if (do_coord) { sXd[tid] = 0.f; sXd[TE+tid] = 0.f; sXd[2*TE+tid] = 0.f; }
            }
        }
        __syncthreads();

        // phase B: coalesced gather, 8 threads per row-half
        // f1 = silu(Ps[src] + Pd[dst] + radial*w1r), stored k-major
        {
            const int g = tid >> 3, q8 = tid & 7;
#pragma unroll
            for (int pass = 0; pass < 4; pass++) {
                int el = pass * 32 + g;
                int s = sSrc[el];
                int d = sDst[el]; if (d < 0) d = 0;
                float rad = sRad[el];
                const float* ps = Ps + (size_t)s*C;
                const float* pd = Pd + (size_t)d*C;
#pragma unroll
                for (int hh = 0; hh < 2; hh++) {
                    int k = hh*32 + q8*4;
                    float4 a = *reinterpret_cast<const float4*>(ps + k);
                    float4 b = *reinterpret_cast<const float4*>(pd + k);
                    float4 w = *reinterpret_cast<const float4*>(sW1r + k);
                    sA[(k+0)*SAS + swz(k+0, el)] = siluf(a.x + b.x + rad*w.x);
                    sA[(k+1)*SAS + swz(k+1, el)] = siluf(a.y + b.y + rad*w.y);
                    sA[(k+2)*SAS + swz(k+2, el)] = siluf(a.z + b.z + rad*w.z);
                    sA[(k+3)*SAS + swz(k+3, el)] = siluf(a.w + b.w + rad*w.w);
                }
            }
        }
        __syncthreads();

        // GEMM2: msg_h = silu(f1 @ W2 + b2)
        Acc acc;
        init_bias(acc, sB2, tx8);
        gemm_tile<C, SAS, C>(sA, sW2, ty4, tx8, acc);
        float mh[4][8];
        unpack_acc(acc, mh);
        silu_r(mh);

        // quad-merged scatter (dst sorted)
        {
            int d0 = sDst[ty4+0], d1 = sDst[ty4+1], d2 = sDst[ty4+2], d3 = sDst[ty4+3];
            float v[8];
#pragma unroll
            for (int c = 0; c < 8; c++) v[c] = mh[0][c];
            int dcur = d0;
#pragma unroll
            for (int i = 1; i < 4; i++) {
                int d = (i == 1) ? d1 : (i == 2) ? d2 : d3;
                if (d == dcur) {
#pragma unroll
                    for (int c = 0; c < 8; c++) v[c] += mh[i][c];
                } else {
                    if (dcur >= 0) {
                        float* p = hn + (size_t)dcur*C + tx8;
                        redv4(p,     v[0], v[1], v[2], v[3]);
                        redv4(p + 4, v[4], v[5], v[6], v[7]);
                    }
                    dcur = d;
#pragma unroll
                    for (int c = 0; c < 8; c++) v[c] = mh[i][c];
                }
            }
            if (dcur >= 0) {
                float* p = hn + (size_t)dcur*C + tx8;
                redv4(p,     v[0], v[1], v[2], v[3]);
                redv4(p + 4, v[4], v[5], v[6], v[7]);
            }
        }

        if (!do_coord) continue;

        __syncthreads();
        store_t<SAS>(sA, ty4, tx8, mh);
        __syncthreads();

        // GEMM3: q = silu(msg_h @ CW1 + cb1); coord_s = q . cw2
        init_bias(acc, sCB1, tx8);
        gemm_tile<C, SAS, C>(sA, sC1, ty4, tx8, acc);
        float q[4][8];
        unpack_acc(acc, q);
        silu_r(q);
        float c2[8];
#pragma unroll
        for (int j = 0; j < 8; j++) c2[j] = sC2[tx8 + j];
        float csum[4];
#pragma unroll
        for (int i = 0; i < 4; i++) {
            float s = 0.f;
#pragma unroll
            for (int j = 0; j < 8; j++) s += q[i][j] * c2[j];
            csum[i] = s;
        }
#pragma unroll
        for (int m = 1; m < 8; m <<= 1) {
#pragma unroll
            for (int i = 0; i < 4; i++)
                csum[i] += __shfl_xor_sync(0xffffffffu, csum[i], m);
        }
        if ((tid & 7) == 0) {
            int d0 = sDst[ty4+0], d1 = sDst[ty4+1], d2 = sDst[ty4+2], d3 = sDst[ty4+3];
            float vx = csum[0]*sXd[ty4+0], vy = csum[0]*sXd[TE+ty4+0], vz = csum[0]*sXd[2*TE+ty4+0];
            int dcur = d0;
#pragma unroll
            for (int i = 1; i < 4; i++) {
                int el = ty4 + i;
                int d = (i == 1) ? d1 : (i == 2) ? d2 : d3;
                float ax = csum[i]*sXd[el], ay = csum[i]*sXd[TE+el], az = csum[i]*sXd[2*TE+el];
                if (d == dcur) { vx += ax; vy += ay; vz += az; }
                else {
                    if (dcur >= 0) redv4(xs + (size_t)dcur*4, vx, vy, vz, 0.0f);
                    dcur = d; vx = ax; vy = ay; vz = az;
                }
            }
            if (dcur >= 0) redv4(xs + (size_t)dcur*4, vx, vy, vz, 0.0f);
        }
    }
}

// ---------------- node kernel (sH aliases sA rows 0..63 after GEMM1) ----------------
#define NODE_SMEM_FLOATS (2*C*C + C + C*C + C + C + C + 2*C*SAS)
#define NODE_SMEM_BYTES  (NODE_SMEM_FLOATS * 4)

__global__ void __launch_bounds__(BT, 1) node_kernel(
    const float* __restrict__ h, const float* __restrict__ x,
    const float* __restrict__ hn, const float* __restrict__ xs,
    const int* __restrict__ cnt,
    const float* __restrict__ nw1, const float* __restrict__ nb1,
    const float* __restrict__ nw2, const float* __restrict__ nb2,
    const float* __restrict__ lng, const float* __restrict__ lnb,
    float* __restrict__ h_out, float* __restrict__ x_out, int N, int do_x)
{
    extern __shared__ float sm[];
    float* sW1 = sm;
    float* sB1 = sW1 + 2*C*C;
    float* sW2 = sB1 + C;
    float* sB2 = sW2 + C*C;
    float* sLG = sB2 + C;
    float* sLB = sLG + C;
    float* sA  = sLB + C;      // 128 x 132 (k-major, swizzled); rows 0..63 reused as sH
    float* sH  = sA;

    const int tid = threadIdx.x;
    for (int i = tid; i < 2*C*C; i += BT) sW1[i] = nw1[i];
    for (int i = tid; i < C*C; i += BT) sW2[i] = nw2[i];
    if (tid < C) { sB1[tid] = nb1[tid]; sB2[tid] = nb2[tid]; sLG[tid] = lng[tid]; sLB[tid] = lnb[tid]; }

    const int tx8 = (tid & 7) * 8;
    const int ty4 = (tid >> 3) * 4;
    const int base = blockIdx.x * TE;

    if (do_x && tid < TE) {
        int n = base + tid;
        if (n < N) {
            float4 s = *reinterpret_cast<const float4*>(xs + (size_t)n*4);
            float deg = fmaxf((float)cnt[n], 1.0f);
            x_out[3*n+0] = x[3*n+0] + s.x / deg;
            x_out[3*n+1] = x[3*n+1] + s.y / deg;
            x_out[3*n+2] = x[3*n+2] + s.z / deg;
        }
    }

    // stage [h | hn] flat coalesced: h -> rows 0..63, hn -> rows 64..127
    {
        const float4* hg = reinterpret_cast<const float4*>(h  + (size_t)base * C);
        const float4* ng = reinterpret_cast<const float4*>(hn + (size_t)base * C);
        const float4 z4 = make_float4(0.f, 0.f, 0.f, 0.f);
        for (int idx = tid; idx < TE * (C/4); idx += BT) {
            int p = idx * 4;
            int ln = p >> 6;
            int k = p & 63;
            bool v = (base + ln < N);
            float4 vh = v ? hg[idx] : z4;
            float4 vn = v ? ng[idx] : z4;
            sA[(k+0)*SAS + swz(k+0, ln)] = vh.x;
            sA[(k+1)*SAS + swz(k+1, ln)] = vh.y;
            sA[(k+2)*SAS + swz(k+2, ln)] = vh.z;
            sA[(k+3)*SAS + swz(k+3, ln)] = vh.w;
            sA[(C+k+0)*SAS + swz(C+k+0, ln)] = vn.x;
            sA[(C+k+1)*SAS + swz(C+k+1, ln)] = vn.y;
            sA[(C+k+2)*SAS + swz(C+k+2, ln)] = vn.z;
            sA[(C+k+3)*SAS + swz(C+k+3, ln)] = vn.w;
        }
    }
    __syncthreads();

    Acc acc;
    init_bias(acc, sB1, tx8);
    gemm_tile<2*C, SAS, C>(sA, sW1, ty4, tx8, acc);
    __syncthreads();
    float r1[4][8];
    unpack_acc(acc, r1);
    silu_r(r1);
    store_t<SAS>(sH, ty4, tx8, r1);   // overwrites sA rows 0..63 (safe after barrier)
    __syncthreads();

    init_bias(acc, sB2, tx8);
    gemm_tile<C, SAS, C>(sH, sW2, ty4, tx8, acc);
    float r2[4][8];
    unpack_acc(acc, r2);

#pragma unroll
    for (int i = 0; i < 4; i++) {
        float s1 = 0.f, s2 = 0.f;
#pragma unroll
        for (int c = 0; c < 8; c++) {
            float v = r2[i][c];
            v = 0.5f * v * (1.0f + erff(v * 0.70710678118654752f));
            r2[i][c] = v;
            s1 += v; s2 += v*v;
        }
#pragma unroll
        for (int m = 1; m < 8; m <<= 1) {
            s1 += __shfl_xor_sync(0xffffffffu, s1, m);
            s2 += __shfl_xor_sync(0xffffffffu, s2, m);
        }
        float mu = s1 * (1.0f / C);
        float var = s2 * (1.0f / C) - mu * mu;
        float inv = rsqrtf(var + 1e-5f);
        int n = base + ty4 + i;
        if (n < N) {
            float o[8];
#pragma unroll
            for (int c = 0; c < 8; c++)
                o[c] = (r2[i][c] - mu) * inv * sLG[tx8 + c] + sLB[tx8 + c];
            float* p = h_out + (size_t)n*C + tx8;
            *reinterpret_cast<float4*>(p)     = make_float4(o[0], o[1], o[2], o[3]);
            *reinterpret_cast<float4*>(p + 4) = make_float4(o[4], o[5], o[6], o[7]);
        }
    }
}

// ---------------- output head ----------------
#define OTILE 256
#define OAS 260
#define OUT_SMEM_FLOATS (C*OAS + C*NOUTC + NOUTC)
#define OUT_SMEM_BYTES  (OUT_SMEM_FLOATS * 4)

__global__ void __launch_bounds__(BT, 2) out_kernel(
    const float* __restrict__ h, const float* __restrict__ ow,
    const float* __restrict__ ob, float* __restrict__ out, int N)
{
    extern __shared__ float sm[];
    float* sA = sm;
    float* sW = sA + C*OAS;
    float* sB = sW + C*NOUTC;

    const int tid = threadIdx.x;
    for (int i = tid; i < C*NOUTC; i += BT) sW[i] = ow[i];
    if (tid < NOUTC) sB[tid] = ob[tid];

    const int base = blockIdx.x * OTILE;
    {
        const float4* hg = reinterpret_cast<const float4*>(h + (size_t)base * C);
        const float4 z4 = make_float4(0.f, 0.f, 0.f, 0.f);
        for (int idx = tid; idx < OTILE * (C/4); idx += BT) {
            int p = idx * 4;
            int ln = p >> 6;
            int k = p & 63;
            float4 v = (base + ln < N) ? hg[idx] : z4;
            sA[(k+0)*OAS + swz(k+0, ln)] = v.x;
            sA[(k+1)*OAS + swz(k+1, ln)] = v.y;
            sA[(k+2)*OAS + swz(k+2, ln)] = v.z;
            sA[(k+3)*OAS + swz(k+3, ln)] = v.w;
        }
    }
    __syncthreads();

    const int tx8 = (tid & 3) * 8;
    const int ty4 = (tid >> 2) * 4;
    Acc acc;
    init_bias(acc, sB, tx8);
    gemm_tile<C, OAS, NOUTC>(sA, sW, ty4, tx8, acc);
    float r[4][8];
    unpack_acc(acc, r);
#pragma unroll
    for (int i = 0; i < 4; i++) {
        int n = base + ty4 + i;
        if (n < N) {
            float* p = out + (size_t)n * NOUTC + tx8;
            *reinterpret_cast<float4*>(p)     = make_float4(r[i][0], r[i][1], r[i][2], r[i][3]);
            *reinterpret_cast<float4*>(p + 4) = make_float4(r[i][4], r[i][5], r[i][6], r[i][7]);
        }
    }
}

// ---------------- launch ----------------
extern "C" void kernel_launch(void* const* d_in, const int* in_sizes, int n_in,
                              void* d_out, int out_size) {
    const float* node_feat = (const float*)d_in[0];
    const float* xyz = (const float*)d_in[1];
    const int* src = (const int*)d_in[2];
    const int* dst = (const int*)d_in[3];
    const float* ew1 = (const float*)d_in[4];
    const float* eb1 = (const float*)d_in[5];
    const float* ew2 = (const float*)d_in[6];
    const float* eb2 = (const float*)d_in[7];
    const float* cw1 = (const float*)d_in[8];
    const float* cb1 = (const float*)d_in[9];
    const float* cw2 = (const float*)d_in[10];
    const float* nw1 = (const float*)d_in[11];
    const float* nb1 = (const float*)d_in[12];
    const float* nw2 = (const float*)d_in[13];
    const float* nb2 = (const float*)d_in[14];
    const float* lng = (const float*)d_in[15];
    const float* lnb = (const float*)d_in[16];
    const float* ow  = (const float*)d_in[17];
    const float* ob  = (const float*)d_in[18];

    const int N = in_sizes[0] / C;
    const int E = in_sizes[2];

    float *hA, *hB, *xA, *hn, *xs, *Ps, *Pd;
    int *cnt, *cur, *off, *bsum, *esrc, *edst;
    cudaGetSymbolAddress((void**)&hA, g_hA);
    cudaGetSymbolAddress((void**)&hB, g_hB);
    cudaGetSymbolAddress((void**)&xA, g_xA);
    cudaGetSymbolAddress((void**)&hn, g_hn);
    cudaGetSymbolAddress((void**)&xs, g_xs);
    cudaGetSymbolAddress((void**)&Ps, g_Ps);
    cudaGetSymbolAddress((void**)&Pd, g_Pd);
    cudaGetSymbolAddress((void**)&cnt, g_cnt);
    cudaGetSymbolAddress((void**)&cur, g_cur);
    cudaGetSymbolAddress((void**)&off, g_off);
    cudaGetSymbolAddress((void**)&bsum, g_bsum);
    cudaGetSymbolAddress((void**)&esrc, g_esrc);
    cudaGetSymbolAddress((void**)&edst, g_edst);

    cudaFuncSetAttribute(pre_kernel,  cudaFuncAttributeMaxDynamicSharedMemorySize, PRE_SMEM_BYTES);
    cudaFuncSetAttribute(edge_kernel, cudaFuncAttributeMaxDynamicSharedMemorySize, EDGE_SMEM_BYTES);
    cudaFuncSetAttribute(node_kernel, cudaFuncAttributeMaxDynamicSharedMemorySize, NODE_SMEM_BYTES);
    cudaFuncSetAttribute(out_kernel,  cudaFuncAttributeMaxDynamicSharedMemorySize, OUT_SMEM_BYTES);

    const int ntiles_n = (N + TE - 1) / TE;
    const int ntiles_o = (N + OTILE - 1) / OTILE;
    const int nb = (N + SCB - 1) / SCB;

    // counting sort of edges by dst -> packed esrc/edst (reused by both layers)
    zero_int_kernel<<<(N + 255) / 256, 256>>>(cnt, cur, N);
    hist_kernel<<<(E + 255) / 256, 256>>>(dst, cnt, E);
    scan1_kernel<<<nb, 256>>>(cnt, off, bsum, N);
    scan2_kernel<<<1, 128>>>(bsum, nb);
    scatter_kernel<<<(E + 255) / 256, 256>>>(src, dst, off, bsum, cur, esrc, edst, E);

    // layer 0
    pre_kernel<<<ntiles_n, BT, PRE_SMEM_BYTES>>>(node_feat, ew1, eb1, Ps, Pd, N);
    zero_kernel<<<512, 256>>>(hn, xs, N*C, N*4);
    edge_kernel<<<296, BT, EDGE_SMEM_BYTES>>>(Ps, Pd, ew1 + 128*C, xyz, esrc, edst,
        ew2, eb2, cw1, cb1, cw2, hn, xs, E, 1);
    node_kernel<<<ntiles_n, BT, NODE_SMEM_BYTES>>>(node_feat, xyz, hn, xs, cnt,
        nw1, nb1, nw2, nb2, lng, lnb, hA, xA, N, 1);

    // layer 1 (coord path + x update dead w.r.t. output -> skipped)
    pre_kernel<<<ntiles_n, BT, PRE_SMEM_BYTES>>>(hA, ew1 + 129*C, eb1 + C, Ps, Pd, N);
    zero_kernel<<<512, 256>>>(hn, xs, N*C, 0);
    edge_kernel<<<296, BT, EDGE_SMEM_BYTES>>>(Ps, Pd, ew1 + 129*C + 128*C, xA, esrc, edst,
        ew2 + C*C, eb2 + C, cw1 + C*C, cb1 + C, cw2 + C, hn, xs, E, 0);
    node_kernel<<<ntiles_n, BT, NODE_SMEM_BYTES>>>(hA, xA, hn, xs, cnt,
        nw1 + 2*C*C, nb1 + C, nw2 + C*C, nb2 + C, lng, lnb, hB, xA, N, 0);

    out_kernel<<<ntiles_o, BT, OUT_SMEM_BYTES>>>(hB, ow, ob, (float*)d_out, N);
}